// round 3
// baseline (speedup 1.0000x reference)
#include <cuda_runtime.h>
#include <cuda_bf16.h>
#include <cstdint>

#define DD 128
#define MAX_R 8
#define MAX_N 50000
#define NG 9           // 8 relations + self (W0)

// ---------------- device scratch (no allocs allowed) ----------------
__device__ float          g_xw[(size_t)MAX_R * MAX_N * DD];      // XW[r] fp32, 204.8 MB
__device__ __nv_bfloat16  g_xhi[(size_t)MAX_N * DD];             // bf16 hi(X), [m][k]
__device__ __nv_bfloat16  g_xlo[(size_t)MAX_N * DD];             // bf16 lo(X)
__device__ __nv_bfloat16  g_bhi[(size_t)NG * DD * DD];           // Wt hi, [g][n][k]
__device__ __nv_bfloat16  g_blo[(size_t)NG * DD * DD];           // Wt lo

__device__ __forceinline__ uint32_t smem_u32(const void* p) {
    uint32_t a;
    asm("{ .reg .u64 t; cvta.to.shared.u64 t, %1; cvt.u32.u64 %0, t; }" : "=r"(a) : "l"(p));
    return a;
}

// ---------------- conversion kernels ----------------
__global__ void convert_x_kernel(const float* __restrict__ X, int total) {
    int i = blockIdx.x * blockDim.x + threadIdx.x;
    if (i >= total) return;
    float x = X[i];
    __nv_bfloat16 hi = __float2bfloat16_rn(x);
    __nv_bfloat16 lo = __float2bfloat16_rn(x - __bfloat162float(hi));
    g_xhi[i] = hi;
    g_xlo[i] = lo;
}

__global__ void convert_w_kernel(const float* __restrict__ W, const float* __restrict__ W0) {
    int i = blockIdx.x * blockDim.x + threadIdx.x;
    if (i >= NG * DD * DD) return;
    int g = i / (DD * DD);
    int rem = i - g * DD * DD;
    int n = rem >> 7, k = rem & 127;                 // dest layout [g][n][k]
    float w = (g < MAX_R) ? W[(size_t)g * DD * DD + (size_t)k * DD + n]
                          : W0[(size_t)k * DD + n];
    __nv_bfloat16 hi = __float2bfloat16_rn(w);
    __nv_bfloat16 lo = __float2bfloat16_rn(w - __bfloat162float(hi));
    g_bhi[i] = hi;
    g_blo[i] = lo;
}

// ---------------- mma.sync GEMM ----------------
// smem: four 32KB tiles (128 rows x 256B), XOR-swizzled 16B granules.
#define SA_HI 0
#define SA_LO 32768
#define SB_HI 65536
#define SB_LO 98304
#define SMEM_TOTAL 131072

__device__ __forceinline__ void ldmx4(uint32_t* r, uint32_t addr) {
    asm volatile("ldmatrix.sync.aligned.m8n8.x4.shared.b16 {%0,%1,%2,%3}, [%4];"
                 : "=r"(r[0]), "=r"(r[1]), "=r"(r[2]), "=r"(r[3]) : "r"(addr));
}
__device__ __forceinline__ void mma16816(float* c, const uint32_t* a,
                                         uint32_t b0, uint32_t b1) {
    asm volatile("mma.sync.aligned.m16n8k16.row.col.f32.bf16.bf16.f32 "
                 "{%0,%1,%2,%3}, {%4,%5,%6,%7}, {%8,%9}, {%0,%1,%2,%3};"
                 : "+f"(c[0]), "+f"(c[1]), "+f"(c[2]), "+f"(c[3])
                 : "r"(a[0]), "r"(a[1]), "r"(a[2]), "r"(a[3]), "r"(b0), "r"(b1));
}

// CTA: 128(M) x 128(N) fp32 tile of C = A * B^T for weight group g = blockIdx.y.
// A = X split (hi/lo), B = Wt split (hi/lo), 3-term compensated product.
__global__ __launch_bounds__(256, 1)
void gemm_mma_kernel(float* __restrict__ out, int N) {
    extern __shared__ char smem[];
    uint32_t sb = smem_u32(smem);
    const int t = threadIdx.x, ln = t & 31, wid = t >> 5;
    const int row0 = blockIdx.x * 128;
    const int g = blockIdx.y;
    const __nv_bfloat16* bh = g_bhi + (size_t)g * DD * DD;
    const __nv_bfloat16* bl = g_blo + (size_t)g * DD * DD;

    // cooperative load: 2048 x 16B chunks per buffer
    for (int ci = t; ci < 2048; ci += 256) {
        int row = ci >> 4;
        int kb = (ci & 15) * 16;                               // byte offset in row
        uint32_t dst = (uint32_t)(row * 256 + (kb ^ ((row & 7) << 4)));
        int col = kb >> 1;                                     // bf16 column
        int gr = row0 + row;
        uint4 vh = make_uint4(0, 0, 0, 0), vl = vh;
        if (gr < N) {
            vh = *(const uint4*)(g_xhi + (size_t)gr * DD + col);
            vl = *(const uint4*)(g_xlo + (size_t)gr * DD + col);
        }
        *(uint4*)(smem + SA_HI + dst) = vh;
        *(uint4*)(smem + SA_LO + dst) = vl;
        *(uint4*)(smem + SB_HI + dst) = *(const uint4*)(bh + (size_t)row * DD + col);
        *(uint4*)(smem + SB_LO + dst) = *(const uint4*)(bl + (size_t)row * DD + col);
    }
    __syncthreads();

    const int m0 = (wid & 3) * 32;     // 4 M-warps
    const int n0 = (wid >> 2) * 64;    // 2 N-warps

    float c[2][8][4];
    #pragma unroll
    for (int mi = 0; mi < 2; ++mi)
        #pragma unroll
        for (int j = 0; j < 8; ++j)
            #pragma unroll
            for (int q = 0; q < 4; ++q) c[mi][j][q] = 0.f;

    const int rA   = ln & 15;          // ldmatrix row-in-16
    const int koff = ln & 16;          // 16B half-select (k 0-7 vs 8-15)

    #pragma unroll
    for (int term = 0; term < 3; ++term) {
        uint32_t aBase = sb + (term == 2 ? SA_LO : SA_HI);
        uint32_t bBase = sb + (term == 1 ? SB_LO : SB_HI);
        #pragma unroll
        for (int ks = 0; ks < 8; ++ks) {
            int kb = ks * 32;
            uint32_t a[8];
            {
                int r = m0 + rA;
                ldmx4(a + 0, aBase + r * 256 + ((kb + koff) ^ ((r & 7) << 4)));
            }
            {
                int r = m0 + 16 + rA;
                ldmx4(a + 4, aBase + r * 256 + ((kb + koff) ^ ((r & 7) << 4)));
            }
            uint32_t b[16];
            #pragma unroll
            for (int j = 0; j < 4; ++j) {
                int r = n0 + j * 16 + rA;
                ldmx4(b + j * 4, bBase + r * 256 + ((kb + koff) ^ ((r & 7) << 4)));
            }
            #pragma unroll
            for (int mi = 0; mi < 2; ++mi)
                #pragma unroll
                for (int j = 0; j < 4; ++j) {
                    mma16816(c[mi][2 * j],     a + mi * 4, b[j * 4 + 0], b[j * 4 + 2]);
                    mma16816(c[mi][2 * j + 1], a + mi * 4, b[j * 4 + 1], b[j * 4 + 3]);
                }
        }
    }

    float* C = (g < MAX_R) ? (g_xw + (size_t)g * (size_t)N * DD) : out;
    #pragma unroll
    for (int mi = 0; mi < 2; ++mi) {
        int r0 = row0 + m0 + mi * 16 + (ln >> 2);
        #pragma unroll
        for (int j = 0; j < 8; ++j) {
            int col = n0 + j * 8 + (ln & 3) * 2;
            if (r0 < N)
                *(float2*)(C + (size_t)r0 * DD + col) = make_float2(c[mi][j][0], c[mi][j][1]);
            if (r0 + 8 < N)
                *(float2*)(C + (size_t)(r0 + 8) * DD + col) = make_float2(c[mi][j][2], c[mi][j][3]);
        }
    }
}

// ---------------- edge scatter: 4 edges per warp, batched prefetch ----------------
#define EPW 4
__global__ void scatter_kernel(const int* __restrict__ esrc,
                               const int* __restrict__ edst,
                               const int* __restrict__ erel,
                               const float* __restrict__ inv_norm,
                               float* __restrict__ out, int E, int N)
{
    int warp = blockIdx.x * (blockDim.x >> 5) + (threadIdx.x >> 5);
    int lane = threadIdx.x & 31;
    int e0 = warp * EPW;

    float4 v[EPW];
    float  sc[EPW];
    int    dd[EPW];
    #pragma unroll
    for (int i = 0; i < EPW; ++i) {
        int e = e0 + i;
        if (e < E) {
            int s = __ldg(&esrc[e]);
            int d = __ldg(&edst[e]);
            int r = __ldg(&erel[e]);
            sc[i] = __ldg(&inv_norm[(size_t)r * N + d]);
            v[i]  = __ldg((const float4*)(g_xw + ((size_t)r * N + s) * DD) + lane);
            dd[i] = d;
        } else dd[i] = -1;
    }
    #pragma unroll
    for (int i = 0; i < EPW; ++i) {
        if (dd[i] >= 0) {
            float* o = out + (size_t)dd[i] * DD + lane * 4;
            asm volatile("red.global.add.v4.f32 [%0], {%1, %2, %3, %4};"
                         :: "l"(o),
                            "f"(v[i].x * sc[i]), "f"(v[i].y * sc[i]),
                            "f"(v[i].z * sc[i]), "f"(v[i].w * sc[i]) : "memory");
        }
    }
}

extern "C" void kernel_launch(void* const* d_in, const int* in_sizes, int n_in,
                              void* d_out, int out_size)
{
    const float* X        = (const float*)d_in[0];
    const float* W        = (const float*)d_in[1];
    const float* W0       = (const float*)d_in[2];
    const float* inv_norm = (const float*)d_in[3];
    const int*   esrc     = (const int*)d_in[4];
    const int*   edst     = (const int*)d_in[5];
    const int*   erel     = (const int*)d_in[6];
    float* out = (float*)d_out;

    int N = in_sizes[0] / DD;            // 50000
    int E = in_sizes[4];                 // 800000

    // Phase 0: bf16 hi/lo splits
    int totalX = N * DD;
    convert_x_kernel<<<(totalX + 255) / 256, 256>>>(X, totalX);
    convert_w_kernel<<<(NG * DD * DD + 255) / 256, 256>>>(W, W0);

    // Phase 1: tensor-core GEMMs (XW[r] for r<8, out = X @ W0 for g==8)
    cudaFuncSetAttribute(gemm_mma_kernel, cudaFuncAttributeMaxDynamicSharedMemorySize, SMEM_TOTAL);
    dim3 grid((N + 127) / 128, NG);
    gemm_mma_kernel<<<grid, 256, SMEM_TOTAL>>>(out, N);

    // Phase 2: edge scatter-accumulate
    int warps_needed = (E + EPW - 1) / EPW;
    int blocks = (warps_needed + 7) / 8;
    scatter_kernel<<<blocks, 256>>>(esrc, edst, erel, inv_norm, out, E, N);
}

// round 4
// speedup vs baseline: 2.1098x; 2.1098x over previous
#include <cuda_runtime.h>
#include <cuda_fp16.h>
#include <cstdint>

#define DD 128
#define MAX_R 8
#define MAX_N 50000
#define NG 9           // 8 relations + self (W0)

// ---------------- device scratch (no allocs allowed) ----------------
__device__ __half g_xw16[(size_t)MAX_R * MAX_N * DD];   // XW[r] fp16, 102.4 MB
__device__ __half g_xhi[(size_t)MAX_N * DD];            // fp16 hi(X), [m][k]
__device__ __half g_xlo[(size_t)MAX_N * DD];            // fp16 lo(X)
__device__ __half g_wh [(size_t)NG * DD * DD];          // fp16 W^T, [g][n][k]

__device__ __forceinline__ uint32_t smem_u32(const void* p) {
    uint32_t a;
    asm("{ .reg .u64 t; cvta.to.shared.u64 t, %1; cvt.u32.u64 %0, t; }" : "=r"(a) : "l"(p));
    return a;
}

// ---------------- conversion kernels ----------------
__global__ void convert_x_kernel(const float* __restrict__ X, int total) {
    int i = blockIdx.x * blockDim.x + threadIdx.x;
    if (i >= total) return;
    float x = X[i];
    __half hi = __float2half_rn(x);
    __half lo = __float2half_rn(x - __half2float(hi));
    g_xhi[i] = hi;
    g_xlo[i] = lo;
}

__global__ void convert_w_kernel(const float* __restrict__ W, const float* __restrict__ W0) {
    int i = blockIdx.x * blockDim.x + threadIdx.x;
    if (i >= NG * DD * DD) return;
    int g = i / (DD * DD);
    int rem = i - g * DD * DD;
    int n = rem >> 7, k = rem & 127;                 // dest layout [g][n][k]
    float w = (g < MAX_R) ? W[(size_t)g * DD * DD + (size_t)k * DD + n]
                          : W0[(size_t)k * DD + n];
    g_wh[i] = __float2half_rn(w);
}

// ---------------- mma.sync fp16 GEMM, 2-term compensated ----------------
// smem: three 32KB tiles (128 rows x 256B), XOR-swizzled 16B granules.
#define SA_HI 0
#define SA_LO 32768
#define SB    65536
#define SMEM_TOTAL 98304

__device__ __forceinline__ void ldmx4(uint32_t* r, uint32_t addr) {
    asm volatile("ldmatrix.sync.aligned.m8n8.x4.shared.b16 {%0,%1,%2,%3}, [%4];"
                 : "=r"(r[0]), "=r"(r[1]), "=r"(r[2]), "=r"(r[3]) : "r"(addr));
}
__device__ __forceinline__ void mma16816h(float* c, const uint32_t* a,
                                          uint32_t b0, uint32_t b1) {
    asm volatile("mma.sync.aligned.m16n8k16.row.col.f32.f16.f16.f32 "
                 "{%0,%1,%2,%3}, {%4,%5,%6,%7}, {%8,%9}, {%0,%1,%2,%3};"
                 : "+f"(c[0]), "+f"(c[1]), "+f"(c[2]), "+f"(c[3])
                 : "r"(a[0]), "r"(a[1]), "r"(a[2]), "r"(a[3]), "r"(b0), "r"(b1));
}

// CTA: 128(M) x 128(N) tile of C = X * Wt[g]^T.  blockIdx = (g, tile).
// C = Xhi*Whi + Xlo*Whi  (== X * Whi exactly in X; W error ~2^-12)
__global__ __launch_bounds__(256, 2)
void gemm_mma_kernel(float* __restrict__ out, int N) {
    extern __shared__ char smem[];
    uint32_t sb = smem_u32(smem);
    const int t = threadIdx.x, ln = t & 31, wid = t >> 5;
    const int g = blockIdx.x;                        // group-minor: 9 g's of one tile adjacent
    const int row0 = blockIdx.y * 128;
    const __half* wp = g_wh + (size_t)g * DD * DD;

    // cooperative load: 2048 x 16B chunks per buffer
    for (int ci = t; ci < 2048; ci += 256) {
        int row = ci >> 4;
        int kb = (ci & 15) * 16;                     // byte offset in row
        uint32_t dst = (uint32_t)(row * 256 + (kb ^ ((row & 7) << 4)));
        int col = kb >> 1;                           // fp16 column
        int gr = row0 + row;
        uint4 vh = make_uint4(0, 0, 0, 0), vl = vh;
        if (gr < N) {
            vh = *(const uint4*)(g_xhi + (size_t)gr * DD + col);
            vl = *(const uint4*)(g_xlo + (size_t)gr * DD + col);
        }
        *(uint4*)(smem + SA_HI + dst) = vh;
        *(uint4*)(smem + SA_LO + dst) = vl;
        *(uint4*)(smem + SB + dst) = *(const uint4*)(wp + (size_t)row * DD + col);
    }
    __syncthreads();

    const int m0 = (wid & 3) * 32;     // 4 M-warps
    const int n0 = (wid >> 2) * 64;    // 2 N-warps

    float c[2][8][4];
    #pragma unroll
    for (int mi = 0; mi < 2; ++mi)
        #pragma unroll
        for (int j = 0; j < 8; ++j)
            #pragma unroll
            for (int q = 0; q < 4; ++q) c[mi][j][q] = 0.f;

    const int rA   = ln & 15;          // ldmatrix row-in-16
    const int koff = ln & 16;          // 16B half-select

    #pragma unroll
    for (int ks = 0; ks < 8; ++ks) {
        int kb = ks * 32;
        uint32_t ah[8], al[8], b[16];
        #pragma unroll
        for (int mi = 0; mi < 2; ++mi) {
            int r = m0 + mi * 16 + rA;
            uint32_t off = r * 256 + ((kb + koff) ^ ((r & 7) << 4));
            ldmx4(ah + mi * 4, sb + SA_HI + off);
            ldmx4(al + mi * 4, sb + SA_LO + off);
        }
        #pragma unroll
        for (int j = 0; j < 4; ++j) {
            int r = n0 + j * 16 + rA;
            ldmx4(b + j * 4, sb + SB + r * 256 + ((kb + koff) ^ ((r & 7) << 4)));
        }
        #pragma unroll
        for (int mi = 0; mi < 2; ++mi)
            #pragma unroll
            for (int j = 0; j < 4; ++j) {
                mma16816h(c[mi][2 * j],     ah + mi * 4, b[j * 4 + 0], b[j * 4 + 2]);
                mma16816h(c[mi][2 * j + 1], ah + mi * 4, b[j * 4 + 1], b[j * 4 + 3]);
                mma16816h(c[mi][2 * j],     al + mi * 4, b[j * 4 + 0], b[j * 4 + 2]);
                mma16816h(c[mi][2 * j + 1], al + mi * 4, b[j * 4 + 1], b[j * 4 + 3]);
            }
    }

    if (g < MAX_R) {
        // store fp16 XW (halves scatter gather traffic)
        __half* C = g_xw16 + (size_t)g * (size_t)N * DD;
        #pragma unroll
        for (int mi = 0; mi < 2; ++mi) {
            int r0 = row0 + m0 + mi * 16 + (ln >> 2);
            #pragma unroll
            for (int j = 0; j < 8; ++j) {
                int col = n0 + j * 8 + (ln & 3) * 2;
                if (r0 < N)
                    *(__half2*)(C + (size_t)r0 * DD + col) =
                        __floats2half2_rn(c[mi][j][0], c[mi][j][1]);
                if (r0 + 8 < N)
                    *(__half2*)(C + (size_t)(r0 + 8) * DD + col) =
                        __floats2half2_rn(c[mi][j][2], c[mi][j][3]);
            }
        }
    } else {
        // self-connection: fp32 into out
        #pragma unroll
        for (int mi = 0; mi < 2; ++mi) {
            int r0 = row0 + m0 + mi * 16 + (ln >> 2);
            #pragma unroll
            for (int j = 0; j < 8; ++j) {
                int col = n0 + j * 8 + (ln & 3) * 2;
                if (r0 < N)
                    *(float2*)(out + (size_t)r0 * DD + col) = make_float2(c[mi][j][0], c[mi][j][1]);
                if (r0 + 8 < N)
                    *(float2*)(out + (size_t)(r0 + 8) * DD + col) = make_float2(c[mi][j][2], c[mi][j][3]);
            }
        }
    }
}

// ---------------- edge scatter: fp16 gather rows (256B), fp32 red ----------------
#define EPW 2
__global__ void scatter_kernel(const int* __restrict__ esrc,
                               const int* __restrict__ edst,
                               const int* __restrict__ erel,
                               const float* __restrict__ inv_norm,
                               float* __restrict__ out, int E, int N)
{
    int warp = blockIdx.x * (blockDim.x >> 5) + (threadIdx.x >> 5);
    int lane = threadIdx.x & 31;
    int e0 = warp * EPW;

    uint2  v[EPW];
    float  sc[EPW];
    int    dd[EPW];
    #pragma unroll
    for (int i = 0; i < EPW; ++i) {
        int e = e0 + i;
        if (e < E) {
            int s = __ldg(&esrc[e]);
            int d = __ldg(&edst[e]);
            int r = __ldg(&erel[e]);
            sc[i] = __ldg(&inv_norm[(size_t)r * N + d]);
            v[i]  = __ldg((const uint2*)(g_xw16 + ((size_t)r * N + s) * DD) + lane);
            dd[i] = d;
        } else dd[i] = -1;
    }
    #pragma unroll
    for (int i = 0; i < EPW; ++i) {
        if (dd[i] >= 0) {
            float2 f01 = __half22float2(*(__half2*)&v[i].x);
            float2 f23 = __half22float2(*(__half2*)&v[i].y);
            float* o = out + (size_t)dd[i] * DD + lane * 4;
            asm volatile("red.global.add.v4.f32 [%0], {%1, %2, %3, %4};"
                         :: "l"(o),
                            "f"(f01.x * sc[i]), "f"(f01.y * sc[i]),
                            "f"(f23.x * sc[i]), "f"(f23.y * sc[i]) : "memory");
        }
    }
}

extern "C" void kernel_launch(void* const* d_in, const int* in_sizes, int n_in,
                              void* d_out, int out_size)
{
    const float* X        = (const float*)d_in[0];
    const float* W        = (const float*)d_in[1];
    const float* W0       = (const float*)d_in[2];
    const float* inv_norm = (const float*)d_in[3];
    const int*   esrc     = (const int*)d_in[4];
    const int*   edst     = (const int*)d_in[5];
    const int*   erel     = (const int*)d_in[6];
    float* out = (float*)d_out;

    int N = in_sizes[0] / DD;            // 50000
    int E = in_sizes[4];                 // 800000

    // Phase 0: fp16 hi/lo split of X; fp16 transposed weights
    int totalX = N * DD;
    convert_x_kernel<<<(totalX + 255) / 256, 256>>>(X, totalX);
    convert_w_kernel<<<(NG * DD * DD + 255) / 256, 256>>>(W, W0);

    // Phase 1: tensor-core GEMMs. blockIdx.x = group (9), blockIdx.y = M-tile,
    // so the 9 groups of one tile are adjacent -> X tile reads hit L2 8/9 times.
    cudaFuncSetAttribute(gemm_mma_kernel, cudaFuncAttributeMaxDynamicSharedMemorySize, SMEM_TOTAL);
    dim3 grid(NG, (N + 127) / 128);
    gemm_mma_kernel<<<grid, 256, SMEM_TOTAL>>>(out, N);

    // Phase 2: edge scatter-accumulate
    int warps_needed = (E + EPW - 1) / EPW;
    int blocks = (warps_needed + 7) / 8;
    scatter_kernel<<<blocks, 256>>>(esrc, edst, erel, inv_norm, out, E, N);
}

// round 7
// speedup vs baseline: 2.9423x; 1.3946x over previous
#include <cuda_runtime.h>
#include <cuda_fp16.h>
#include <cstdint>

#define DD 128
#define MAX_R 8
#define MAX_N 50000
#define NG 9           // 8 relations + self (W0)

// ---------------- device scratch (no allocs allowed) ----------------
__device__ __half g_agg[(size_t)MAX_R * MAX_N * DD];    // per-(rel,dst) fp16 sums, 102.4 MB
__device__ __half g_x16[(size_t)MAX_N * DD];            // fp16 X, 12.8 MB (L2-resident)
__device__ __half g_wh [(size_t)NG * DD * DD];          // fp16 W^T, [g][n][k]

__device__ __forceinline__ uint32_t smem_u32(const void* p) {
    uint32_t a;
    asm("{ .reg .u64 t; cvta.to.shared.u64 t, %1; cvt.u32.u64 %0, t; }" : "=r"(a) : "l"(p));
    return a;
}

// ---------------- prep kernels ----------------
__global__ void zero_agg_kernel() {
    size_t i = (size_t)blockIdx.x * blockDim.x + threadIdx.x;   // one uint4 (8 halves) each
    ((uint4*)g_agg)[i] = make_uint4(0, 0, 0, 0);
}

__global__ void convert_x_kernel(const float* __restrict__ X, int total) {
    int i = blockIdx.x * blockDim.x + threadIdx.x;
    if (i >= total) return;
    g_x16[i] = __float2half_rn(X[i]);
}

__global__ void convert_w_kernel(const float* __restrict__ W, const float* __restrict__ W0) {
    int i = blockIdx.x * blockDim.x + threadIdx.x;
    if (i >= NG * DD * DD) return;
    int g = i / (DD * DD);
    int rem = i - g * DD * DD;
    int n = rem >> 7, k = rem & 127;                 // dest layout [g][n][k]
    float w = (g < MAX_R) ? W[(size_t)g * DD * DD + (size_t)k * DD + n]
                          : W0[(size_t)k * DD + n];
    g_wh[i] = __float2half_rn(w);
}

// ---------------- edge scatter: agg[r,dst] += X16[src] ----------------
// Half-warp per edge: 16 lanes x 16B = 256B row; red.v4.f16x2 = 16B atomic ops
// (12.8M ops total). Gather source g_x16 is 12.8 MB -> fully L2-resident.
__global__ void scatter_kernel(const int* __restrict__ esrc,
                               const int* __restrict__ edst,
                               const int* __restrict__ erel,
                               int E, int N)
{
    int warp = blockIdx.x * (blockDim.x >> 5) + (threadIdx.x >> 5);
    int lane = threadIdx.x & 31;
    int e = warp * 2 + (lane >> 4);
    if (e >= E) return;
    int half = lane & 15;

    int s = __ldg(&esrc[e]);
    int d = __ldg(&edst[e]);
    int r = __ldg(&erel[e]);

    uint4 v = __ldg((const uint4*)(g_x16 + (size_t)s * DD) + half);
    __half* o = g_agg + ((size_t)r * N + d) * DD + half * 8;
    asm volatile("red.global.add.noftz.v4.f16x2 [%0], {%1, %2, %3, %4};"
                 :: "l"(o), "r"(v.x), "r"(v.y), "r"(v.z), "r"(v.w) : "memory");
}

// ---------------- fused GEMM: out = X@W0 + sum_r diag(inv_norm_r) agg_r @ W_r ----------------
// smem: A double buffer (2x32KB) + B double buffer (2x32KB) = 128KB
#define SMEM_TOTAL 131072

__device__ __forceinline__ void ldmx4(uint32_t* r, uint32_t addr) {
    asm volatile("ldmatrix.sync.aligned.m8n8.x4.shared.b16 {%0,%1,%2,%3}, [%4];"
                 : "=r"(r[0]), "=r"(r[1]), "=r"(r[2]), "=r"(r[3]) : "r"(addr));
}
__device__ __forceinline__ void mma16816h(float* c, const uint32_t* a,
                                          uint32_t b0, uint32_t b1) {
    asm volatile("mma.sync.aligned.m16n8k16.row.col.f32.f16.f16.f32 "
                 "{%0,%1,%2,%3}, {%4,%5,%6,%7}, {%8,%9}, {%0,%1,%2,%3};"
                 : "+f"(c[0]), "+f"(c[1]), "+f"(c[2]), "+f"(c[3])
                 : "r"(a[0]), "r"(a[1]), "r"(a[2]), "r"(a[3]), "r"(b0), "r"(b1));
}

__global__ __launch_bounds__(256, 1)
void gemm_fused_kernel(const float* __restrict__ inv_norm,
                       float* __restrict__ out, int N)
{
    extern __shared__ char smem[];
    uint32_t sb = smem_u32(smem);
    const int t = threadIdx.x, ln = t & 31, wid = t >> 5;
    const int row0 = blockIdx.x * 128;

    // loader geometry: fixed 16B chunk per thread, rows stride 16
    const int kb  = (t & 15) * 16;           // byte offset in 256B row
    const int col = kb >> 1;                 // half index
    const int rbase = t >> 4;                // row 0..15, +16*it

    float c[2][8][4];
    #pragma unroll
    for (int mi = 0; mi < 2; ++mi)
        #pragma unroll
        for (int j = 0; j < 8; ++j)
            #pragma unroll
            for (int q = 0; q < 4; ++q) c[mi][j][q] = 0.f;

    uint4 aReg[8], bReg[8];
    float sReg[8];

    // ---- fetch group g into registers ----
    auto fetch = [&](int g) {
        const __half* A = (g < MAX_R) ? (g_agg + (size_t)g * (size_t)N * DD) : g_x16;
        const __half* B = g_wh + (size_t)g * DD * DD;
        #pragma unroll
        for (int it = 0; it < 8; ++it) {
            int row = rbase + it * 16;
            int gr = row0 + row;
            if (gr < N) {
                aReg[it] = *(const uint4*)(A + (size_t)gr * DD + col);
                sReg[it] = (g < MAX_R) ? __ldg(&inv_norm[(size_t)g * N + gr]) : 1.f;
            } else {
                aReg[it] = make_uint4(0, 0, 0, 0);
                sReg[it] = 0.f;
            }
            bReg[it] = *(const uint4*)(B + (size_t)row * DD + col);
        }
    };
    // ---- store staged registers into smem buffer p (A scaled by inv_norm) ----
    auto sts = [&](int p) {
        char* aBuf = smem + p * 32768;
        char* bBuf = smem + 65536 + p * 32768;
        #pragma unroll
        for (int it = 0; it < 8; ++it) {
            int row = rbase + it * 16;
            uint32_t dst = (uint32_t)(row * 256 + (kb ^ ((row & 7) << 4)));
            __half2 s2 = __float2half2_rn(sReg[it]);
            uint4 av = aReg[it];
            *(__half2*)&av.x = __hmul2(*(__half2*)&av.x, s2);
            *(__half2*)&av.y = __hmul2(*(__half2*)&av.y, s2);
            *(__half2*)&av.z = __hmul2(*(__half2*)&av.z, s2);
            *(__half2*)&av.w = __hmul2(*(__half2*)&av.w, s2);
            *(uint4*)(aBuf + dst) = av;
            *(uint4*)(bBuf + dst) = bReg[it];
        }
    };

    const int m0 = (wid & 3) * 32;     // 4 M-warps
    const int n0 = (wid >> 2) * 64;    // 2 N-warps
    const int rA   = ln & 15;
    const int koff = ln & 16;

    fetch(0);
    sts(0);
    __syncthreads();

    for (int g = 0; g < NG; ++g) {
        if (g + 1 < NG) fetch(g + 1);          // LDGs in flight under MMAs

        uint32_t aBase = sb + (g & 1) * 32768;
        uint32_t bBase = sb + 65536 + (g & 1) * 32768;
        #pragma unroll
        for (int ks = 0; ks < 8; ++ks) {
            int kbb = ks * 32;
            uint32_t ah[8], b[16];
            #pragma unroll
            for (int mi = 0; mi < 2; ++mi) {
                int r = m0 + mi * 16 + rA;
                ldmx4(ah + mi * 4, aBase + r * 256 + ((kbb + koff) ^ ((r & 7) << 4)));
            }
            #pragma unroll
            for (int j = 0; j < 4; ++j) {
                int r = n0 + j * 16 + rA;
                ldmx4(b + j * 4, bBase + r * 256 + ((kbb + koff) ^ ((r & 7) << 4)));
            }
            #pragma unroll
            for (int mi = 0; mi < 2; ++mi)
                #pragma unroll
                for (int j = 0; j < 4; ++j) {
                    mma16816h(c[mi][2 * j],     ah + mi * 4, b[j * 4 + 0], b[j * 4 + 2]);
                    mma16816h(c[mi][2 * j + 1], ah + mi * 4, b[j * 4 + 1], b[j * 4 + 3]);
                }
        }

        if (g + 1 < NG) {
            __syncthreads();                   // all readers done with alt buffer
            sts((g + 1) & 1);
            __syncthreads();
        }
    }

    // epilogue: fp32 result -> out
    #pragma unroll
    for (int mi = 0; mi < 2; ++mi) {
        int r0 = row0 + m0 + mi * 16 + (ln >> 2);
        #pragma unroll
        for (int j = 0; j < 8; ++j) {
            int colo = n0 + j * 8 + (ln & 3) * 2;
            if (r0 < N)
                *(float2*)(out + (size_t)r0 * DD + colo) = make_float2(c[mi][j][0], c[mi][j][1]);
            if (r0 + 8 < N)
                *(float2*)(out + (size_t)(r0 + 8) * DD + colo) = make_float2(c[mi][j][2], c[mi][j][3]);
        }
    }
}

extern "C" void kernel_launch(void* const* d_in, const int* in_sizes, int n_in,
                              void* d_out, int out_size)
{
    const float* X        = (const float*)d_in[0];
    const float* W        = (const float*)d_in[1];
    const float* W0       = (const float*)d_in[2];
    const float* inv_norm = (const float*)d_in[3];
    const int*   esrc     = (const int*)d_in[4];
    const int*   edst     = (const int*)d_in[5];
    const int*   erel     = (const int*)d_in[6];
    float* out = (float*)d_out;

    int N = in_sizes[0] / DD;            // 50000
    int E = in_sizes[4];                 // 800000

    // Phase 0: zero agg, fp16 X, fp16 transposed weights
    size_t aggU4 = (size_t)MAX_R * MAX_N * DD / 8;          // 6.4M uint4
    zero_agg_kernel<<<(unsigned)((aggU4 + 255) / 256), 256>>>();
    int totalX = N * DD;
    convert_x_kernel<<<(totalX + 255) / 256, 256>>>(X, totalX);
    convert_w_kernel<<<(NG * DD * DD + 255) / 256, 256>>>(W, W0);

    // Phase 1: scatter raw X rows into agg (gather side fully L2-resident)
    int edges_per_block = (256 / 32) * 2;   // 8 warps x 2 edges
    scatter_kernel<<<(E + edges_per_block - 1) / edges_per_block, 256>>>(esrc, edst, erel, E, N);

    // Phase 2: fused GEMM — out = X@W0 + sum_r diag(inv_norm_r) agg_r @ W_r
    cudaFuncSetAttribute(gemm_fused_kernel, cudaFuncAttributeMaxDynamicSharedMemorySize, SMEM_TOTAL);
    gemm_fused_kernel<<<(N + 127) / 128, 256, SMEM_TOTAL>>>(inv_norm, out, N);
}

// round 8
// speedup vs baseline: 3.5897x; 1.2200x over previous
#include <cuda_runtime.h>
#include <cuda_fp16.h>
#include <cstdint>

#define DD 128
#define MAX_R 8
#define MAX_N 50000
#define NG 9           // 8 relations + self (W0)

// ---------------- device scratch (no allocs allowed) ----------------
__device__ __half g_agg[(size_t)MAX_R * MAX_N * DD];    // pre-scaled per-(rel,dst) sums, 102.4 MB
__device__ __half g_x16[(size_t)MAX_N * DD];            // fp16 X, 12.8 MB (L2-resident)
__device__ __half g_wh [(size_t)NG * DD * DD];          // fp16 W^T, [g][n][k]

__device__ __forceinline__ uint32_t smem_u32(const void* p) {
    uint32_t a;
    asm("{ .reg .u64 t; cvta.to.shared.u64 t, %1; cvt.u32.u64 %0, t; }" : "=r"(a) : "l"(p));
    return a;
}

// ---------------- fused prep: zero agg + fp16(X) + fp16(W^T) ----------------
#define ZA ((int)((size_t)MAX_R * MAX_N * DD / 8))      // 6,400,000 uint4 zero items
#define XC (MAX_N * DD / 8)                             // 800,000 x-convert items (8 floats each)
#define WC (NG * DD * DD)                               // 147,456 w-convert scalars
__global__ void prep_kernel(const float* __restrict__ X,
                            const float* __restrict__ W,
                            const float* __restrict__ W0)
{
    int i = blockIdx.x * blockDim.x + threadIdx.x;
    if (i < ZA) {
        ((uint4*)g_agg)[i] = make_uint4(0, 0, 0, 0);
    } else if (i < ZA + XC) {
        int j = i - ZA;                                  // 8 floats -> 8 halves (one uint4)
        float4 f0 = ((const float4*)X)[j * 2];
        float4 f1 = ((const float4*)X)[j * 2 + 1];
        uint4 o;
        *(__half2*)&o.x = __floats2half2_rn(f0.x, f0.y);
        *(__half2*)&o.y = __floats2half2_rn(f0.z, f0.w);
        *(__half2*)&o.z = __floats2half2_rn(f1.x, f1.y);
        *(__half2*)&o.w = __floats2half2_rn(f1.z, f1.w);
        ((uint4*)g_x16)[j] = o;
    } else if (i < ZA + XC + WC) {
        int j = i - ZA - XC;
        int g = j / (DD * DD);
        int rem = j - g * DD * DD;
        int n = rem >> 7, k = rem & 127;                 // dest layout [g][n][k]
        float w = (g < MAX_R) ? W[(size_t)g * DD * DD + (size_t)k * DD + n]
                              : W0[(size_t)k * DD + n];
        g_wh[j] = __float2half_rn(w);
    }
}

// ---------------- edge scatter: agg[r,dst] += inv_norm[r,dst] * X16[src] ----------------
// Half-warp per edge, 2 edges batched per half-warp (MLP=2 on L2-resident gathers).
__global__ void scatter_kernel(const int* __restrict__ esrc,
                               const int* __restrict__ edst,
                               const int* __restrict__ erel,
                               const float* __restrict__ inv_norm,
                               int E, int N)
{
    int warp = blockIdx.x * (blockDim.x >> 5) + (threadIdx.x >> 5);
    int lane = threadIdx.x & 31;
    int h = lane >> 4;              // half-warp id
    int half = lane & 15;
    int e0 = warp * 4;

    uint4 v[2];
    __half2 s2[2];
    long long off[2];
    #pragma unroll
    for (int i = 0; i < 2; ++i) {
        int e = e0 + i * 2 + h;
        if (e < E) {
            int s = __ldg(&esrc[e]);
            int d = __ldg(&edst[e]);
            int r = __ldg(&erel[e]);
            float sc = __ldg(&inv_norm[(size_t)r * N + d]);
            s2[i] = __float2half2_rn(sc);
            v[i]  = __ldg((const uint4*)(g_x16 + (size_t)s * DD) + half);
            off[i] = ((long long)r * N + d) * DD + half * 8;
        } else off[i] = -1;
    }
    #pragma unroll
    for (int i = 0; i < 2; ++i) {
        if (off[i] >= 0) {
            uint4 av = v[i];
            *(__half2*)&av.x = __hmul2(*(__half2*)&av.x, s2[i]);
            *(__half2*)&av.y = __hmul2(*(__half2*)&av.y, s2[i]);
            *(__half2*)&av.z = __hmul2(*(__half2*)&av.z, s2[i]);
            *(__half2*)&av.w = __hmul2(*(__half2*)&av.w, s2[i]);
            asm volatile("red.global.add.noftz.v4.f16x2 [%0], {%1, %2, %3, %4};"
                         :: "l"(g_agg + off[i]), "r"(av.x), "r"(av.y), "r"(av.z), "r"(av.w)
                         : "memory");
        }
    }
}

// ---------------- GEMM: out = X@W0 + sum_r agg_r @ W_r  (agg pre-scaled) ----------------
// cp.async 2-stage pipeline: stage = [A 32KB][B 32KB], 2 stages = 128KB.
#define STAGE_BYTES 65536
#define SMEM_TOTAL  131072

__device__ __forceinline__ void cp16(uint32_t dst, const void* src, int bytes) {
    asm volatile("cp.async.cg.shared.global [%0], [%1], 16, %2;"
                 :: "r"(dst), "l"(src), "r"(bytes) : "memory");
}
#define CP_COMMIT() asm volatile("cp.async.commit_group;" ::: "memory")
#define CP_WAIT(n)  asm volatile("cp.async.wait_group %0;" :: "n"(n) : "memory")

__device__ __forceinline__ void ldmx4(uint32_t* r, uint32_t addr) {
    asm volatile("ldmatrix.sync.aligned.m8n8.x4.shared.b16 {%0,%1,%2,%3}, [%4];"
                 : "=r"(r[0]), "=r"(r[1]), "=r"(r[2]), "=r"(r[3]) : "r"(addr));
}
__device__ __forceinline__ void mma16816h(float* c, const uint32_t* a,
                                          uint32_t b0, uint32_t b1) {
    asm volatile("mma.sync.aligned.m16n8k16.row.col.f32.f16.f16.f32 "
                 "{%0,%1,%2,%3}, {%4,%5,%6,%7}, {%8,%9}, {%0,%1,%2,%3};"
                 : "+f"(c[0]), "+f"(c[1]), "+f"(c[2]), "+f"(c[3])
                 : "r"(a[0]), "r"(a[1]), "r"(a[2]), "r"(a[3]), "r"(b0), "r"(b1));
}

__global__ __launch_bounds__(256, 1)
void gemm_fused_kernel(float* __restrict__ out, int N)
{
    extern __shared__ char smem[];
    uint32_t sb = smem_u32(smem);
    const int t = threadIdx.x, ln = t & 31, wid = t >> 5;
    const int row0 = blockIdx.x * 128;

    // loader geometry: 16B chunk per thread, rows stride 16 (8 iters)
    const int kb  = (t & 15) * 16;           // byte offset in 256B row
    const int col = kb >> 1;                 // half index
    const int rbase = t >> 4;                // row 0..15

    auto issue = [&](int g, int buf) {
        const __half* A = (g < MAX_R) ? (g_agg + (size_t)g * (size_t)N * DD) : g_x16;
        const __half* B = g_wh + (size_t)g * DD * DD;
        uint32_t aBuf = sb + buf * STAGE_BYTES;
        uint32_t bBuf = aBuf + 32768;
        #pragma unroll
        for (int it = 0; it < 8; ++it) {
            int row = rbase + it * 16;
            int gr = row0 + row;
            uint32_t dst = (uint32_t)(row * 256 + (kb ^ ((row & 7) << 4)));
            int ok = (gr < N);
            const __half* ap = A + (size_t)(ok ? gr : 0) * DD + col;
            cp16(aBuf + dst, ap, ok ? 16 : 0);           // zero-fill tail rows
            cp16(bBuf + dst, B + (size_t)row * DD + col, 16);
        }
    };

    float c[2][8][4];
    #pragma unroll
    for (int mi = 0; mi < 2; ++mi)
        #pragma unroll
        for (int j = 0; j < 8; ++j)
            #pragma unroll
            for (int q = 0; q < 4; ++q) c[mi][j][q] = 0.f;

    const int m0 = (wid & 3) * 32;     // 4 M-warps
    const int n0 = (wid >> 2) * 64;    // 2 N-warps
    const int rA   = ln & 15;
    const int koff = ln & 16;

    issue(0, 0); CP_COMMIT();
    issue(1, 1); CP_COMMIT();

    for (int g = 0; g < NG; ++g) {
        if (g < NG - 1) { CP_WAIT(1); } else { CP_WAIT(0); }   // stage g resident
        __syncthreads();

        uint32_t aBase = sb + (g & 1) * STAGE_BYTES;
        uint32_t bBase = aBase + 32768;
        #pragma unroll
        for (int ks = 0; ks < 8; ++ks) {
            int kbb = ks * 32;
            uint32_t ah[8], b[16];
            #pragma unroll
            for (int mi = 0; mi < 2; ++mi) {
                int r = m0 + mi * 16 + rA;
                ldmx4(ah + mi * 4, aBase + r * 256 + ((kbb + koff) ^ ((r & 7) << 4)));
            }
            #pragma unroll
            for (int j = 0; j < 4; ++j) {
                int r = n0 + j * 16 + rA;
                ldmx4(b + j * 4, bBase + r * 256 + ((kbb + koff) ^ ((r & 7) << 4)));
            }
            #pragma unroll
            for (int mi = 0; mi < 2; ++mi)
                #pragma unroll
                for (int j = 0; j < 4; ++j) {
                    mma16816h(c[mi][2 * j],     ah + mi * 4, b[j * 4 + 0], b[j * 4 + 2]);
                    mma16816h(c[mi][2 * j + 1], ah + mi * 4, b[j * 4 + 1], b[j * 4 + 3]);
                }
        }
        __syncthreads();                                   // readers done with stage g
        if (g + 2 < NG) { issue(g + 2, g & 1); CP_COMMIT(); }
    }

    // epilogue: fp32 result -> out
    #pragma unroll
    for (int mi = 0; mi < 2; ++mi) {
        int r0 = row0 + m0 + mi * 16 + (ln >> 2);
        #pragma unroll
        for (int j = 0; j < 8; ++j) {
            int colo = n0 + j * 8 + (ln & 3) * 2;
            if (r0 < N)
                *(float2*)(out + (size_t)r0 * DD + colo) = make_float2(c[mi][j][0], c[mi][j][1]);
            if (r0 + 8 < N)
                *(float2*)(out + (size_t)(r0 + 8) * DD + colo) = make_float2(c[mi][j][2], c[mi][j][3]);
        }
    }
}

extern "C" void kernel_launch(void* const* d_in, const int* in_sizes, int n_in,
                              void* d_out, int out_size)
{
    const float* X        = (const float*)d_in[0];
    const float* W        = (const float*)d_in[1];
    const float* W0       = (const float*)d_in[2];
    const float* inv_norm = (const float*)d_in[3];
    const int*   esrc     = (const int*)d_in[4];
    const int*   edst     = (const int*)d_in[5];
    const int*   erel     = (const int*)d_in[6];
    float* out = (float*)d_out;

    int N = in_sizes[0] / DD;            // 50000
    int E = in_sizes[4];                 // 800000

    // Phase 0: fused prep (zero agg + fp16 X + fp16 W^T)
    int prep_items = ZA + XC + WC;
    prep_kernel<<<(prep_items + 255) / 256, 256>>>(X, W, W0);

    // Phase 1: scatter pre-scaled X rows into agg
    int edges_per_block = (256 / 32) * 4;   // 8 warps x 4 edges
    scatter_kernel<<<(E + edges_per_block - 1) / edges_per_block, 256>>>(esrc, edst, erel, inv_norm, E, N);

    // Phase 2: pipelined GEMM — out = X@W0 + sum_r agg_r @ W_r
    cudaFuncSetAttribute(gemm_fused_kernel, cudaFuncAttributeMaxDynamicSharedMemorySize, SMEM_TOTAL);
    gemm_fused_kernel<<<(N + 127) / 128, 256, SMEM_TOTAL>>>(out, N);
}